// round 13
// baseline (speedup 1.0000x reference)
#include <cuda_runtime.h>
#include <cuda_bf16.h>

#define NTHR  256
#define NWARP 8
#define NH    50
#define NNEG  10
#define NROWS 62
#define EDIM  128
#define EV4   32
#define EPS   1e-6f
#define FULL  0xffffffffu

__device__ __forceinline__ float dot4(float4 a, float4 b) {
    return a.x * b.x + a.y * b.y + a.z * b.z + a.w * b.w;
}

__global__ __launch_bounds__(NTHR, 4) void htne_kernel(
    const int*   __restrict__ s_nodes,
    const int*   __restrict__ t_nodes,
    const float* __restrict__ t_times,
    const int*   __restrict__ h_nodes,
    const float* __restrict__ h_times,
    const float* __restrict__ h_mask,
    const int*   __restrict__ n_nodes,
    const float* __restrict__ emb,
    const float* __restrict__ delta_w,
    float*       __restrict__ out,
    int B)
{
    const int tid  = threadIdx.x;
    const int wid  = tid >> 5;
    const int lane = tid & 31;

    __shared__ float4 hb_p[NWARP * 32];  // 4 KB: per-warp hbar partials
    __shared__ float  scal_s[64 * 4];    // [row][0:rr 1:rs 2:rt]
    __shared__ float  nterm_s[NNEG];

    const float4* emb4 = (const float4*)emb;
    const int sub   = lane & 15;
    const int rbase = wid * 2 + (lane >> 4);
    const bool v1   = (lane < NH - 32);
    const int  stride = gridDim.x;

    // ---- prefetch scalar state for the first b ----
    int   sidx, tidx, nodes[4];
    float dm0, dm1;
    {
        const int bn = blockIdx.x;
        sidx = s_nodes[bn];
        tidx = t_nodes[bn];
#pragma unroll
        for (int j = 0; j < 4; j++) {
            const int r = j * 16 + rbase;
            if      (r < NH)  nodes[j] = h_nodes[bn * NH + r];
            else if (r < 60)  nodes[j] = n_nodes[bn * NNEG + (r - 50)];
            else if (r == 60) nodes[j] = sidx;
            else              nodes[j] = tidx;
        }
        const float delta = delta_w[sidx];
        const float ttime = t_times[bn];
        dm0 = __expf(delta * fabsf(ttime - h_times[bn * NH + lane]))
            * h_mask[bn * NH + lane];
        dm1 = 0.f;
        if (v1)
            dm1 = __expf(delta * fabsf(ttime - h_times[bn * NH + lane + 32]))
                * h_mask[bn * NH + lane + 32];
    }

    for (int b = blockIdx.x; b < B; b += stride) {
        // ---- phase 1a: rows straight from prefetched indices (no idx chain) ----
        const float4 s4a = emb4[((unsigned)sidx << 5) + sub];
        const float4 s4b = emb4[((unsigned)sidx << 5) + sub + 16];
        const float4 t4a = emb4[((unsigned)tidx << 5) + sub];
        const float4 t4b = emb4[((unsigned)tidx << 5) + sub + 16];

        float4 r0[4], r1[4];
#pragma unroll
        for (int j = 0; j < 4; j++) {
            const unsigned off = (unsigned)nodes[j] << 5;
            r0[j] = emb4[off + sub];
            r1[j] = emb4[off + sub + 16];
        }

        // ---- phase 1b: 3 dots per row, packed 16-lane reduce ----
#pragma unroll
        for (int j = 0; j < 4; j++) {
            const int r = j * 16 + rbase;
            float a  = dot4(r0[j], r0[j]) + dot4(r1[j], r1[j]);
            float bb = dot4(r0[j], s4a)   + dot4(r1[j], s4b);
            float c  = dot4(r0[j], t4a)   + dot4(r1[j], t4b);
            a  += __shfl_xor_sync(FULL, a, 8);
            bb += __shfl_xor_sync(FULL, bb, 8);
            c  += __shfl_xor_sync(FULL, c, 8);
            a  += __shfl_xor_sync(FULL, a, 4);
            bb += __shfl_xor_sync(FULL, bb, 4);
            c  += __shfl_xor_sync(FULL, c, 4);
            const int g2 = (lane >> 2) & 3;
            float x = (g2 == 0) ? a : (g2 == 1) ? bb : c;
            x += __shfl_xor_sync(FULL, x, 2);
            x += __shfl_xor_sync(FULL, x, 1);
            if ((lane & 3) == 0 && g2 < 3 && r < NROWS)
                scal_s[r * 4 + g2] = x;
        }
        __syncthreads();   // B1

        // ---- softmax (no max-sub; logits in [-0.032, 0]) + weighted reductions ----
        const float src_sq = scal_s[60 * 4 + 0];
        const float tar_sq = scal_s[61 * 4 + 0];
        const float st_dot = scal_s[60 * 4 + 2];

        const float hh0 = scal_s[lane * 4 + 0];
        const float lg0 = -(src_sq + hh0 - 2.0f * scal_s[lane * 4 + 1]);
        const float pa0 = -(tar_sq + hh0 - 2.0f * scal_s[lane * 4 + 2]);
        float hh1 = 0.f, e1 = 0.f, pa1 = 0.f;
        if (v1) {
            const int h1 = lane + 32;
            hh1 = scal_s[h1 * 4 + 0];
            e1  = __expf(-(src_sq + hh1 - 2.0f * scal_s[h1 * 4 + 1]));
            pa1 = -(tar_sq + hh1 - 2.0f * scal_s[h1 * 4 + 2]);
        }
        const float e0 = __expf(lg0);
        const float w0 = e0 * dm0;
        const float w1 = e1 * dm1;

        float S  = e0 + e1;
        float Wn = w0 + w1;
        float Cn = w0 * hh0 + w1 * hh1;
        float Pn = w0 * pa0 + w1 * pa1;

        S  += __shfl_xor_sync(FULL, S, 16);
        Wn += __shfl_xor_sync(FULL, Wn, 16);
        Cn += __shfl_xor_sync(FULL, Cn, 16);
        Pn += __shfl_xor_sync(FULL, Pn, 16);
        S  += __shfl_xor_sync(FULL, S, 8);
        Wn += __shfl_xor_sync(FULL, Wn, 8);
        Cn += __shfl_xor_sync(FULL, Cn, 8);
        Pn += __shfl_xor_sync(FULL, Pn, 8);
        const int g = lane >> 3;
        float x = (g == 0) ? S : (g == 1) ? Wn : (g == 2) ? Cn : Pn;
        x += __shfl_xor_sync(FULL, x, 4);
        x += __shfl_xor_sync(FULL, x, 2);
        x += __shfl_xor_sync(FULL, x, 1);
        const float Sv   = __shfl_sync(FULL, x, 0);
        const float invS = 1.0f / Sv;
        const float Wv   = __shfl_sync(FULL, x, 8)  * invS;
        const float Cv   = __shfl_sync(FULL, x, 16) * invS;
        const float Pv   = __shfl_sync(FULL, x, 24) * invS;

        // ---- hbar partials from REGISTER-held rows ----
        {
            float4 a0 = make_float4(0.f, 0.f, 0.f, 0.f);
            float4 a1 = make_float4(0.f, 0.f, 0.f, 0.f);
#pragma unroll
            for (int j = 0; j < 4; j++) {
                const int r = j * 16 + rbase;
                const float wa = __shfl_sync(FULL, w0, r & 31);
                const float wb = __shfl_sync(FULL, w1, (r - 32) & 31);
                const float w  = (r < 32) ? wa : ((r < NH) ? wb : 0.f);
                a0.x += w * r0[j].x; a0.y += w * r0[j].y;
                a0.z += w * r0[j].z; a0.w += w * r0[j].w;
                a1.x += w * r1[j].x; a1.y += w * r1[j].y;
                a1.z += w * r1[j].z; a1.w += w * r1[j].w;
            }
            a0.x += __shfl_xor_sync(FULL, a0.x, 16);
            a0.y += __shfl_xor_sync(FULL, a0.y, 16);
            a0.z += __shfl_xor_sync(FULL, a0.z, 16);
            a0.w += __shfl_xor_sync(FULL, a0.w, 16);
            a1.x += __shfl_xor_sync(FULL, a1.x, 16);
            a1.y += __shfl_xor_sync(FULL, a1.y, 16);
            a1.z += __shfl_xor_sync(FULL, a1.z, 16);
            a1.w += __shfl_xor_sync(FULL, a1.w, 16);
            if (lane < 16) {
                hb_p[wid * 32 + sub]      = a0;
                hb_p[wid * 32 + 16 + sub] = a1;
            }
        }
        __syncthreads();   // B2

        // ---- prefetch next-b scalar state (overlaps the shuffle-heavy tail) ----
        int   sidx_n = 0, tidx_n = 0, nodes_n[4] = {0, 0, 0, 0};
        float dm0_n = 0.f, dm1_n = 0.f;
        const int bn = b + stride;
        if (bn < B) {
            sidx_n = s_nodes[bn];
            tidx_n = t_nodes[bn];
#pragma unroll
            for (int j = 0; j < 4; j++) {
                const int r = j * 16 + rbase;
                if      (r < NH)  nodes_n[j] = h_nodes[bn * NH + r];
                else if (r < 60)  nodes_n[j] = n_nodes[bn * NNEG + (r - 50)];
                else if (r == 60) nodes_n[j] = sidx_n;
                else              nodes_n[j] = tidx_n;
            }
            const float delta = delta_w[sidx_n];
            const float ttime = t_times[bn];
            dm0_n = __expf(delta * fabsf(ttime - h_times[bn * NH + lane]))
                  * h_mask[bn * NH + lane];
            if (v1)
                dm1_n = __expf(delta * fabsf(ttime - h_times[bn * NH + lane + 32]))
                      * h_mask[bn * NH + lane + 32];
        }

        // ---- tail: combine hbar; negs from REGISTER rows of warps 1..5 ----
        {
            float4 hb4 = make_float4(0.f, 0.f, 0.f, 0.f);
#pragma unroll
            for (int gg = 0; gg < NWARP; gg++) {
                const float4 p = hb_p[gg * 32 + lane];
                hb4.x += p.x; hb4.y += p.y; hb4.z += p.z; hb4.w += p.w;
            }

            if (wid >= 1 && wid <= 5) {
                float4 hb_lo, hb_hi;
                hb_lo.x = __shfl_sync(FULL, hb4.x, sub);
                hb_lo.y = __shfl_sync(FULL, hb4.y, sub);
                hb_lo.z = __shfl_sync(FULL, hb4.z, sub);
                hb_lo.w = __shfl_sync(FULL, hb4.w, sub);
                hb_hi.x = __shfl_sync(FULL, hb4.x, sub + 16);
                hb_hi.y = __shfl_sync(FULL, hb4.y, sub + 16);
                hb_hi.z = __shfl_sync(FULL, hb4.z, sub + 16);
                hb_hi.w = __shfl_sync(FULL, hb4.w, sub + 16);
                float part = dot4(hb_lo, r0[3]) + dot4(hb_hi, r1[3]);
                part += __shfl_xor_sync(FULL, part, 8);
                part += __shfl_xor_sync(FULL, part, 4);
                part += __shfl_xor_sync(FULL, part, 2);
                part += __shfl_xor_sync(FULL, part, 1);
                if (sub == 0) {
                    const int n = 2 * (wid - 1) + (lane >> 4);
                    const float nn = scal_s[(50 + n) * 4 + 0];
                    const float sn = scal_s[(50 + n) * 4 + 1];
                    const float n_mu = -(src_sq + nn - 2.0f * sn);
                    const float nl   = n_mu - Cv - Wv * nn + 2.0f * invS * part;
                    nterm_s[n] = __logf(1.0f / (1.0f + __expf(nl)) + EPS);
                }
            }
        }
        __syncthreads();   // B3

        if (tid == 0) {
            const float p_mu     = -(src_sq + tar_sq - 2.0f * st_dot);
            const float p_lambda = p_mu + Pv;
            const float pos_loss = -__logf(1.0f / (1.0f + __expf(-p_lambda)) + EPS);
            float neg_loss = 0.f;
#pragma unroll
            for (int n = 0; n < NNEG; n++) neg_loss += nterm_s[n];
            out[b] = pos_loss - neg_loss;
        }
        __syncthreads();   // B4: protect smem before next iteration overwrites

        sidx = sidx_n;  tidx = tidx_n;
        nodes[0] = nodes_n[0]; nodes[1] = nodes_n[1];
        nodes[2] = nodes_n[2]; nodes[3] = nodes_n[3];
        dm0 = dm0_n;  dm1 = dm1_n;
    }
}

extern "C" void kernel_launch(void* const* d_in, const int* in_sizes, int n_in,
                              void* d_out, int out_size)
{
    const int*   s_nodes = (const int*)  d_in[0];
    const int*   t_nodes = (const int*)  d_in[1];
    const float* t_times = (const float*)d_in[2];
    const int*   h_nodes = (const int*)  d_in[3];
    const float* h_times = (const float*)d_in[4];
    const float* h_mask  = (const float*)d_in[5];
    const int*   n_nodes = (const int*)  d_in[6];
    const float* emb     = (const float*)d_in[7];
    const float* delta_w = (const float*)d_in[8];
    float*       out     = (float*)d_out;

    const int B = in_sizes[0];
    int grid = 148 * 4;               // persistent: one wave at occupancy 4
    if (grid > B) grid = B;
    htne_kernel<<<grid, NTHR>>>(s_nodes, t_nodes, t_times, h_nodes, h_times,
                                h_mask, n_nodes, emb, delta_w, out, B);
}

// round 14
// speedup vs baseline: 1.0664x; 1.0664x over previous
#include <cuda_runtime.h>
#include <cuda_bf16.h>

#define NTHR  256
#define NWARP 8
#define NH    50
#define NNEG  10
#define NROWS 62
#define EDIM  128
#define EV4   32
#define EPS   1e-6f
#define FULL  0xffffffffu

__device__ __forceinline__ float dot4(float4 a, float4 b) {
    return a.x * b.x + a.y * b.y + a.z * b.z + a.w * b.w;
}

__global__ __launch_bounds__(NTHR, 4) void htne_kernel(
    const int*   __restrict__ s_nodes,
    const int*   __restrict__ t_nodes,
    const float* __restrict__ t_times,
    const int*   __restrict__ h_nodes,
    const float* __restrict__ h_times,
    const float* __restrict__ h_mask,
    const int*   __restrict__ n_nodes,
    const float* __restrict__ emb,
    const float* __restrict__ delta_w,
    float*       __restrict__ out)
{
    const int b    = blockIdx.x;
    const int tid  = threadIdx.x;
    const int wid  = tid >> 5;
    const int lane = tid & 31;

    __shared__ float4 hb_p[NWARP * 32];  // 4 KB: per-warp hbar partials
    __shared__ float  scal_s[64 * 4];    // [row][0:rr 1:rs 2:rt]
    __shared__ float  nterm_s[NNEG];

    const float4* emb4 = (const float4*)emb;
    const int sidx = s_nodes[b];
    const int tidx = t_nodes[b];

    const int sub   = lane & 15;
    const int rbase = wid * 2 + (lane >> 4);   // this lane's row offset

    // ---- hoisted decay: depends only on b — overlaps the gather below ----
    const float delta = delta_w[sidx];
    const float ttime = t_times[b];
    const bool  v1    = (lane < NH - 32);
    const float dm0   = __expf(delta * fabsf(ttime - h_times[b * NH + lane]))
                      * h_mask[b * NH + lane];
    float dm1 = 0.f;
    if (v1)
        dm1 = __expf(delta * fabsf(ttime - h_times[b * NH + lane + 32]))
            * h_mask[b * NH + lane + 32];

    const float4 s4a = emb4[((unsigned)sidx << 5) + sub];
    const float4 s4b = emb4[((unsigned)sidx << 5) + sub + 16];
    const float4 t4a = emb4[((unsigned)tidx << 5) + sub];
    const float4 t4b = emb4[((unsigned)tidx << 5) + sub + 16];

    // ---- phase 1a: gather all 8 rows of this warp into registers (MLP 8) ----
    float4 r0[4], r1[4];
#pragma unroll
    for (int j = 0; j < 4; j++) {
        const int r = j * 16 + rbase;
        int node;
        if      (r < NH)  node = h_nodes[b * NH + r];
        else if (r < 60)  node = n_nodes[b * NNEG + (r - 50)];
        else if (r == 60) node = sidx;
        else              node = tidx;
        const unsigned off = (unsigned)node << 5;   // node * EV4
        r0[j] = emb4[off + sub];
        r1[j] = emb4[off + sub + 16];
    }

    // ---- phase 1b: 3 dots per row, packed 16-lane reduce (8 shfl / 2 rows) ----
#pragma unroll
    for (int j = 0; j < 4; j++) {
        const int r = j * 16 + rbase;
        float a  = dot4(r0[j], r0[j]) + dot4(r1[j], r1[j]);
        float bb = dot4(r0[j], s4a)   + dot4(r1[j], s4b);
        float c  = dot4(r0[j], t4a)   + dot4(r1[j], t4b);
        a  += __shfl_xor_sync(FULL, a, 8);
        bb += __shfl_xor_sync(FULL, bb, 8);
        c  += __shfl_xor_sync(FULL, c, 8);
        a  += __shfl_xor_sync(FULL, a, 4);
        bb += __shfl_xor_sync(FULL, bb, 4);
        c  += __shfl_xor_sync(FULL, c, 4);
        const int g2 = (lane >> 2) & 3;
        float x = (g2 == 0) ? a : (g2 == 1) ? bb : c;
        x += __shfl_xor_sync(FULL, x, 2);
        x += __shfl_xor_sync(FULL, x, 1);
        if ((lane & 3) == 0 && g2 < 3 && r < NROWS)
            scal_s[r * 4 + g2] = x;
    }
    __syncthreads();   // B1

    // ---- softmax (no max-sub: logits in [-0.032, 0]) + weighted reductions ----
    const float src_sq = scal_s[60 * 4 + 0];
    const float tar_sq = scal_s[61 * 4 + 0];
    const float st_dot = scal_s[60 * 4 + 2];

    const float hh0 = scal_s[lane * 4 + 0];
    const float lg0 = -(src_sq + hh0 - 2.0f * scal_s[lane * 4 + 1]);
    const float pa0 = -(tar_sq + hh0 - 2.0f * scal_s[lane * 4 + 2]);
    float hh1 = 0.f, e1 = 0.f, pa1 = 0.f;
    if (v1) {
        const int h1 = lane + 32;
        hh1 = scal_s[h1 * 4 + 0];
        e1  = __expf(-(src_sq + hh1 - 2.0f * scal_s[h1 * 4 + 1]));
        pa1 = -(tar_sq + hh1 - 2.0f * scal_s[h1 * 4 + 2]);
    }
    const float e0 = __expf(lg0);
    const float w0 = e0 * dm0;
    const float w1 = e1 * dm1;

    float S  = e0 + e1;
    float Wn = w0 + w1;
    float Cn = w0 * hh0 + w1 * hh1;
    float Pn = w0 * pa0 + w1 * pa1;

    S  += __shfl_xor_sync(FULL, S, 16);
    Wn += __shfl_xor_sync(FULL, Wn, 16);
    Cn += __shfl_xor_sync(FULL, Cn, 16);
    Pn += __shfl_xor_sync(FULL, Pn, 16);
    S  += __shfl_xor_sync(FULL, S, 8);
    Wn += __shfl_xor_sync(FULL, Wn, 8);
    Cn += __shfl_xor_sync(FULL, Cn, 8);
    Pn += __shfl_xor_sync(FULL, Pn, 8);
    const int g = lane >> 3;
    float x = (g == 0) ? S : (g == 1) ? Wn : (g == 2) ? Cn : Pn;
    x += __shfl_xor_sync(FULL, x, 4);
    x += __shfl_xor_sync(FULL, x, 2);
    x += __shfl_xor_sync(FULL, x, 1);
    const float Sv   = __shfl_sync(FULL, x, 0);
    const float invS = 1.0f / Sv;
    const float Wv   = __shfl_sync(FULL, x, 8)  * invS;
    const float Cv   = __shfl_sync(FULL, x, 16) * invS;
    const float Pv   = __shfl_sync(FULL, x, 24) * invS;

    // ---- hbar partials from REGISTER-held rows (zero gmem traffic) ----
    {
        float4 a0 = make_float4(0.f, 0.f, 0.f, 0.f);
        float4 a1 = make_float4(0.f, 0.f, 0.f, 0.f);
#pragma unroll
        for (int j = 0; j < 4; j++) {
            const int r = j * 16 + rbase;
            const float wa = __shfl_sync(FULL, w0, r & 31);
            const float wb = __shfl_sync(FULL, w1, (r - 32) & 31);
            const float w  = (r < 32) ? wa : ((r < NH) ? wb : 0.f);
            a0.x += w * r0[j].x; a0.y += w * r0[j].y;
            a0.z += w * r0[j].z; a0.w += w * r0[j].w;
            a1.x += w * r1[j].x; a1.y += w * r1[j].y;
            a1.z += w * r1[j].z; a1.w += w * r1[j].w;
        }
        a0.x += __shfl_xor_sync(FULL, a0.x, 16);
        a0.y += __shfl_xor_sync(FULL, a0.y, 16);
        a0.z += __shfl_xor_sync(FULL, a0.z, 16);
        a0.w += __shfl_xor_sync(FULL, a0.w, 16);
        a1.x += __shfl_xor_sync(FULL, a1.x, 16);
        a1.y += __shfl_xor_sync(FULL, a1.y, 16);
        a1.z += __shfl_xor_sync(FULL, a1.z, 16);
        a1.w += __shfl_xor_sync(FULL, a1.w, 16);
        if (lane < 16) {
            hb_p[wid * 32 + sub]      = a0;   // element groups 0..15
            hb_p[wid * 32 + 16 + sub] = a1;   // element groups 16..31
        }
    }
    __syncthreads();   // B2

    // ---- tail: only warps 0..5 participate; warps 6,7 are done ----
    if (wid >= 1 && wid <= 5) {
        // combine hbar (only consumers do this work)
        float4 hb4 = make_float4(0.f, 0.f, 0.f, 0.f);
#pragma unroll
        for (int gg = 0; gg < NWARP; gg++) {
            const float4 p = hb_p[gg * 32 + lane];
            hb4.x += p.x; hb4.y += p.y; hb4.z += p.z; hb4.w += p.w;
        }
        // lanes 0-15 need hb elements of groups sub, lanes 16-31 groups sub+16
        float4 hb_lo, hb_hi;
        hb_lo.x = __shfl_sync(FULL, hb4.x, sub);
        hb_lo.y = __shfl_sync(FULL, hb4.y, sub);
        hb_lo.z = __shfl_sync(FULL, hb4.z, sub);
        hb_lo.w = __shfl_sync(FULL, hb4.w, sub);
        hb_hi.x = __shfl_sync(FULL, hb4.x, sub + 16);
        hb_hi.y = __shfl_sync(FULL, hb4.y, sub + 16);
        hb_hi.z = __shfl_sync(FULL, hb4.z, sub + 16);
        hb_hi.w = __shfl_sync(FULL, hb4.w, sub + 16);
        float part = dot4(hb_lo, r0[3]) + dot4(hb_hi, r1[3]);
        part += __shfl_xor_sync(FULL, part, 8);
        part += __shfl_xor_sync(FULL, part, 4);
        part += __shfl_xor_sync(FULL, part, 2);
        part += __shfl_xor_sync(FULL, part, 1);
        if (sub == 0) {
            const int n = 2 * (wid - 1) + (lane >> 4);
            const float nn = scal_s[(50 + n) * 4 + 0];
            const float sn = scal_s[(50 + n) * 4 + 1];
            const float n_mu = -(src_sq + nn - 2.0f * sn);
            const float nl   = n_mu - Cv - Wv * nn + 2.0f * invS * part;
            nterm_s[n] = __logf(1.0f / (1.0f + __expf(nl)) + EPS);
        }
    }

    // named barrier over warps 0..5 only (192 threads); warps 6,7 exit
    if (wid < 6) {
        asm volatile("bar.sync 1, 192;" ::: "memory");
        if (tid == 0) {
            const float p_mu     = -(src_sq + tar_sq - 2.0f * st_dot);
            const float p_lambda = p_mu + Pv;
            const float pos_loss = -__logf(1.0f / (1.0f + __expf(-p_lambda)) + EPS);
            float neg_loss = 0.f;
#pragma unroll
            for (int n = 0; n < NNEG; n++) neg_loss += nterm_s[n];
            out[b] = pos_loss - neg_loss;
        }
    }
}

extern "C" void kernel_launch(void* const* d_in, const int* in_sizes, int n_in,
                              void* d_out, int out_size)
{
    const int*   s_nodes = (const int*)  d_in[0];
    const int*   t_nodes = (const int*)  d_in[1];
    const float* t_times = (const float*)d_in[2];
    const int*   h_nodes = (const int*)  d_in[3];
    const float* h_times = (const float*)d_in[4];
    const float* h_mask  = (const float*)d_in[5];
    const int*   n_nodes = (const int*)  d_in[6];
    const float* emb     = (const float*)d_in[7];
    const float* delta_w = (const float*)d_in[8];
    float*       out     = (float*)d_out;

    const int B = in_sizes[0];
    htne_kernel<<<B, NTHR>>>(s_nodes, t_nodes, t_times, h_nodes, h_times,
                             h_mask, n_nodes, emb, delta_w, out);
}

// round 15
// speedup vs baseline: 1.0674x; 1.0010x over previous
#include <cuda_runtime.h>
#include <cuda_bf16.h>

#define NTHR  256
#define NWARP 8
#define NH    50
#define NNEG  10
#define NROWS 62
#define EDIM  128
#define EV4   32
#define EPS   1e-6f
#define FULL  0xffffffffu

__device__ __forceinline__ float dot4(float4 a, float4 b) {
    return a.x * b.x + a.y * b.y + a.z * b.z + a.w * b.w;
}

__global__ __launch_bounds__(NTHR, 4) void htne_kernel(
    const int*   __restrict__ s_nodes,
    const int*   __restrict__ t_nodes,
    const float* __restrict__ t_times,
    const int*   __restrict__ h_nodes,
    const float* __restrict__ h_times,
    const float* __restrict__ h_mask,
    const int*   __restrict__ n_nodes,
    const float* __restrict__ emb,
    const float* __restrict__ delta_w,
    float*       __restrict__ out)
{
    const int b    = blockIdx.x;
    const int tid  = threadIdx.x;
    const int wid  = tid >> 5;
    const int lane = tid & 31;

    __shared__ float4 hb_p[NWARP * 32];  // 4 KB: per-warp hbar partials
    __shared__ float  scal_s[3 * 64];    // SoA: [0]=rr [1]=rs [2]=rt, 64 rows each
    __shared__ float  nterm_s[NNEG];

    const float4* emb4 = (const float4*)emb;
    const int sidx = s_nodes[b];
    const int tidx = t_nodes[b];

    const int sub   = lane & 15;
    const int rbase = wid * 2 + (lane >> 4);   // this lane's row offset

    // ---- hoisted decay: depends only on b — overlaps the gather below ----
    const float delta = delta_w[sidx];
    const float ttime = t_times[b];
    const bool  v1    = (lane < NH - 32);
    const float dm0   = __expf(delta * fabsf(ttime - h_times[b * NH + lane]))
                      * h_mask[b * NH + lane];
    float dm1 = 0.f;
    if (v1)
        dm1 = __expf(delta * fabsf(ttime - h_times[b * NH + lane + 32]))
            * h_mask[b * NH + lane + 32];

    const float4 s4a = emb4[((unsigned)sidx << 5) + sub];
    const float4 s4b = emb4[((unsigned)sidx << 5) + sub + 16];
    const float4 t4a = emb4[((unsigned)tidx << 5) + sub];
    const float4 t4b = emb4[((unsigned)tidx << 5) + sub + 16];

    // ---- phase 1a: gather all 8 rows of this warp into registers (MLP 8) ----
    float4 r0[4], r1[4];
#pragma unroll
    for (int j = 0; j < 4; j++) {
        const int r = j * 16 + rbase;
        int node;
        if      (r < NH)  node = h_nodes[b * NH + r];
        else if (r < 60)  node = n_nodes[b * NNEG + (r - 50)];
        else if (r == 60) node = sidx;
        else              node = tidx;
        const unsigned off = (unsigned)node << 5;   // node * EV4
        r0[j] = emb4[off + sub];
        r1[j] = emb4[off + sub + 16];
    }

    // ---- phase 1b: 3 dots per row, packed 16-lane reduce (8 shfl / 2 rows) ----
#pragma unroll
    for (int j = 0; j < 4; j++) {
        const int r = j * 16 + rbase;
        float a  = dot4(r0[j], r0[j]) + dot4(r1[j], r1[j]);
        float bb = dot4(r0[j], s4a)   + dot4(r1[j], s4b);
        float c  = dot4(r0[j], t4a)   + dot4(r1[j], t4b);
        a  += __shfl_xor_sync(FULL, a, 8);
        bb += __shfl_xor_sync(FULL, bb, 8);
        c  += __shfl_xor_sync(FULL, c, 8);
        a  += __shfl_xor_sync(FULL, a, 4);
        bb += __shfl_xor_sync(FULL, bb, 4);
        c  += __shfl_xor_sync(FULL, c, 4);
        const int g2 = (lane >> 2) & 3;
        float x = (g2 == 0) ? a : (g2 == 1) ? bb : c;
        x += __shfl_xor_sync(FULL, x, 2);
        x += __shfl_xor_sync(FULL, x, 1);
        if ((lane & 3) == 0 && g2 < 3 && r < NROWS)
            scal_s[g2 * 64 + r] = x;     // SoA store
    }
    __syncthreads();   // B1

    // ---- softmax (no max-sub: logits in [-0.032, 0]) + weighted reductions ----
    const float src_sq = scal_s[0 * 64 + 60];
    const float tar_sq = scal_s[0 * 64 + 61];
    const float st_dot = scal_s[2 * 64 + 60];

    const float hh0 = scal_s[0 * 64 + lane];                  // stride-1 LDS
    const float lg0 = -(src_sq + hh0 - 2.0f * scal_s[1 * 64 + lane]);
    const float pa0 = -(tar_sq + hh0 - 2.0f * scal_s[2 * 64 + lane]);
    float hh1 = 0.f, e1 = 0.f, pa1 = 0.f;
    if (v1) {
        const int h1 = lane + 32;
        hh1 = scal_s[0 * 64 + h1];
        e1  = __expf(-(src_sq + hh1 - 2.0f * scal_s[1 * 64 + h1]));
        pa1 = -(tar_sq + hh1 - 2.0f * scal_s[2 * 64 + h1]);
    }
    const float e0 = __expf(lg0);
    const float w0 = e0 * dm0;
    const float w1 = e1 * dm1;

    float S  = e0 + e1;
    float Wn = w0 + w1;
    float Cn = w0 * hh0 + w1 * hh1;
    float Pn = w0 * pa0 + w1 * pa1;

    S  += __shfl_xor_sync(FULL, S, 16);
    Wn += __shfl_xor_sync(FULL, Wn, 16);
    Cn += __shfl_xor_sync(FULL, Cn, 16);
    Pn += __shfl_xor_sync(FULL, Pn, 16);
    S  += __shfl_xor_sync(FULL, S, 8);
    Wn += __shfl_xor_sync(FULL, Wn, 8);
    Cn += __shfl_xor_sync(FULL, Cn, 8);
    Pn += __shfl_xor_sync(FULL, Pn, 8);
    const int g = lane >> 3;
    float x = (g == 0) ? S : (g == 1) ? Wn : (g == 2) ? Cn : Pn;
    x += __shfl_xor_sync(FULL, x, 4);
    x += __shfl_xor_sync(FULL, x, 2);
    x += __shfl_xor_sync(FULL, x, 1);
    const float Sv   = __shfl_sync(FULL, x, 0);
    const float invS = 1.0f / Sv;
    const float Wv   = __shfl_sync(FULL, x, 8)  * invS;
    const float Cv   = __shfl_sync(FULL, x, 16) * invS;
    const float Pv   = __shfl_sync(FULL, x, 24) * invS;

    // ---- hbar partials from REGISTER-held rows (zero gmem traffic) ----
    {
        float4 a0 = make_float4(0.f, 0.f, 0.f, 0.f);
        float4 a1 = make_float4(0.f, 0.f, 0.f, 0.f);
#pragma unroll
        for (int j = 0; j < 4; j++) {
            const int r = j * 16 + rbase;
            const float wa = __shfl_sync(FULL, w0, r & 31);
            const float wb = __shfl_sync(FULL, w1, (r - 32) & 31);
            const float w  = (r < 32) ? wa : ((r < NH) ? wb : 0.f);
            a0.x += w * r0[j].x; a0.y += w * r0[j].y;
            a0.z += w * r0[j].z; a0.w += w * r0[j].w;
            a1.x += w * r1[j].x; a1.y += w * r1[j].y;
            a1.z += w * r1[j].z; a1.w += w * r1[j].w;
        }
        a0.x += __shfl_xor_sync(FULL, a0.x, 16);
        a0.y += __shfl_xor_sync(FULL, a0.y, 16);
        a0.z += __shfl_xor_sync(FULL, a0.z, 16);
        a0.w += __shfl_xor_sync(FULL, a0.w, 16);
        a1.x += __shfl_xor_sync(FULL, a1.x, 16);
        a1.y += __shfl_xor_sync(FULL, a1.y, 16);
        a1.z += __shfl_xor_sync(FULL, a1.z, 16);
        a1.w += __shfl_xor_sync(FULL, a1.w, 16);
        if (lane < 16) {
            hb_p[wid * 32 + sub]      = a0;   // element groups 0..15
            hb_p[wid * 32 + 16 + sub] = a1;   // element groups 16..31
        }
    }
    __syncthreads();   // B2

    // ---- tail: only warps 1..5 do the negative dot products ----
    if (wid >= 1 && wid <= 5) {
        float4 hb4 = make_float4(0.f, 0.f, 0.f, 0.f);
#pragma unroll
        for (int gg = 0; gg < NWARP; gg++) {
            const float4 p = hb_p[gg * 32 + lane];
            hb4.x += p.x; hb4.y += p.y; hb4.z += p.z; hb4.w += p.w;
        }
        float4 hb_lo, hb_hi;
        hb_lo.x = __shfl_sync(FULL, hb4.x, sub);
        hb_lo.y = __shfl_sync(FULL, hb4.y, sub);
        hb_lo.z = __shfl_sync(FULL, hb4.z, sub);
        hb_lo.w = __shfl_sync(FULL, hb4.w, sub);
        hb_hi.x = __shfl_sync(FULL, hb4.x, sub + 16);
        hb_hi.y = __shfl_sync(FULL, hb4.y, sub + 16);
        hb_hi.z = __shfl_sync(FULL, hb4.z, sub + 16);
        hb_hi.w = __shfl_sync(FULL, hb4.w, sub + 16);
        float part = dot4(hb_lo, r0[3]) + dot4(hb_hi, r1[3]);
        part += __shfl_xor_sync(FULL, part, 8);
        part += __shfl_xor_sync(FULL, part, 4);
        part += __shfl_xor_sync(FULL, part, 2);
        part += __shfl_xor_sync(FULL, part, 1);
        if (sub == 0) {
            const int n = 2 * (wid - 1) + (lane >> 4);
            const float nn = scal_s[0 * 64 + 50 + n];
            const float sn = scal_s[1 * 64 + 50 + n];
            const float n_mu = -(src_sq + nn - 2.0f * sn);
            const float nl   = n_mu - Cv - Wv * nn + 2.0f * invS * part;
            nterm_s[n] = __logf(1.0f / (1.0f + __expf(nl)) + EPS);
        }
    }

    // named barrier over warps 0..5 only (192 threads); warps 6,7 exit
    if (wid < 6) {
        asm volatile("bar.sync 1, 192;" ::: "memory");
        if (tid == 0) {
            const float p_mu     = -(src_sq + tar_sq - 2.0f * st_dot);
            const float p_lambda = p_mu + Pv;
            const float pos_loss = -__logf(1.0f / (1.0f + __expf(-p_lambda)) + EPS);
            float neg_loss = 0.f;
#pragma unroll
            for (int n = 0; n < NNEG; n++) neg_loss += nterm_s[n];
            out[b] = pos_loss - neg_loss;
        }
    }
}

extern "C" void kernel_launch(void* const* d_in, const int* in_sizes, int n_in,
                              void* d_out, int out_size)
{
    const int*   s_nodes = (const int*)  d_in[0];
    const int*   t_nodes = (const int*)  d_in[1];
    const float* t_times = (const float*)d_in[2];
    const int*   h_nodes = (const int*)  d_in[3];
    const float* h_times = (const float*)d_in[4];
    const float* h_mask  = (const float*)d_in[5];
    const int*   n_nodes = (const int*)  d_in[6];
    const float* emb     = (const float*)d_in[7];
    const float* delta_w = (const float*)d_in[8];
    float*       out     = (float*)d_out;

    const int B = in_sizes[0];
    htne_kernel<<<B, NTHR>>>(s_nodes, t_nodes, t_times, h_nodes, h_times,
                             h_mask, n_nodes, emb, delta_w, out);
}